// round 1
// baseline (speedup 1.0000x reference)
#include <cuda_runtime.h>
#include <math.h>

#define EPS 1e-5f

constexpr int Bn = 256;   // batch
constexpr int CT = 256;   // trunk channels
constexpr int CR = 192;   // reg channels
constexpr int CG = 64;    // gpool channels
constexpr int H = 19, W = 19, HW = 361;
constexpr int PADS = 28;      // padded smem row stride (floats), 112B = 16B aligned
constexpr int CCH = 16;       // cin chunk per smem stage
constexpr int COUT_T = 16;    // cout tile per block
constexpr int NTHREADS = 320; // 20 rows * 16 couts; rows 0..18 active

// ---- scratch (device globals; no allocation allowed) ----
__device__ float g_act1[Bn * CT * HW];          // mish(bn1(x))
__device__ float g_reg [Bn * CR * HW];          // conv1a output
__device__ float g_gp  [Bn * CG * HW];          // mish(bn1b(conv1b))
__device__ float g_gpo [Bn * CR];               // gpool @ w_lin.T
__device__ float g_act2[Bn * CR * HW];          // mish(bn2(reg + gpo))
__device__ float g_w1t [16 * CT * 9 * COUT_T];  // conv1 weights, [chunk][cin][k][co16]
__device__ float g_w2t [16 * CR * 9 * COUT_T];  // conv2 weights, same layout

__device__ __forceinline__ float mishf(float x) {
    // x * tanh(softplus(x)) == x * (t^2 + 2t) / (t^2 + 2t + 2), t = e^x
    if (x > 20.f) return x;
    float t = __expf(x);
    float u = fmaf(t, t, 2.f * t);
    return x * __fdividef(u, u + 2.f);
}

// ---- weight transforms: OIHW -> [cout_chunk][cin][k][cout_local] ----
__global__ void k_wt1(const float* __restrict__ w1a, const float* __restrict__ w1b) {
    int i = blockIdx.x * blockDim.x + threadIdx.x;
    if (i >= 16 * CT * 144) return;
    int chunk = i / (CT * 144);
    int rem   = i % (CT * 144);
    int cin   = rem / 144;
    int r2    = rem % 144;
    int k     = r2 / 16;
    int co    = r2 % 16;
    int cout  = chunk * COUT_T + co;
    g_w1t[i] = (cout < CR) ? w1a[(cout * CT + cin) * 9 + k]
                           : w1b[((cout - CR) * CT + cin) * 9 + k];
}

__global__ void k_wt2(const float* __restrict__ w2) {
    int i = blockIdx.x * blockDim.x + threadIdx.x;
    if (i >= 16 * CR * 144) return;
    int chunk = i / (CR * 144);
    int rem   = i % (CR * 144);
    int cin   = rem / 144;
    int r2    = rem % 144;
    int k     = r2 / 16;
    int co    = r2 % 16;
    int cout  = chunk * COUT_T + co;
    g_w2t[i] = w2[(cout * CR + cin) * 9 + k];
}

// ---- stage 1: act1 = mish(bn1(x)) ----
__global__ void k_pre(const float* __restrict__ x,
                      const float* __restrict__ g, const float* __restrict__ b,
                      const float* __restrict__ m, const float* __restrict__ v) {
    int i = blockIdx.x * blockDim.x + threadIdx.x;
    if (i >= Bn * CT * HW) return;
    int c = (i / HW) % CT;
    float sc = g[c] * rsqrtf(v[c] + EPS);
    float bs = fmaf(-m[c], sc, b[c]);
    g_act1[i] = mishf(fmaf(x[i], sc, bs));
}

// ---- 3x3 SAME conv, direct, fp32 ----
// MODE 0: in = g_act1 (CIN=256); cout<192 -> g_reg raw; cout>=192 -> mish(bn1b(.)) -> g_gp
// MODE 1: in = g_act2 (CIN=192); out = conv + resid(x) -> outp (d_out)
template <int CIN, int MODE>
__global__ __launch_bounds__(NTHREADS)
void k_conv(const float* __restrict__ bg, const float* __restrict__ bb,
            const float* __restrict__ bm, const float* __restrict__ bv,
            const float* __restrict__ resid, float* __restrict__ outp) {
    __shared__ __align__(16) float s_in[CCH * 21 * PADS]; // 9408 f = 37632 B
    __shared__ float s_w[CCH * 144];                      // 2304 f = 9216 B

    const float* in = (MODE == 0) ? g_act1 : g_act2;
    const float* wt = (MODE == 0) ? g_w1t : g_w2t;

    const int chunk = blockIdx.x;
    const int img   = blockIdx.y;
    const int tid   = threadIdx.x;
    const int row   = tid / COUT_T;   // image row this thread produces
    const int co    = tid % COUT_T;   // local output channel
    const bool active = (row < H);

    float acc[W];
#pragma unroll
    for (int x = 0; x < W; x++) acc[x] = 0.f;

    const float* inb = in + (size_t)img * CIN * HW;
    const float* wtb = wt + (size_t)chunk * CIN * 144;

    for (int cc = 0; cc < CIN; cc += CCH) {
        // stage input chunk with 1-pixel zero border (rows 21, stride 28)
        for (int i = tid; i < CCH * 21 * PADS; i += NTHREADS) {
            int c   = i / (21 * PADS);
            int rem = i % (21 * PADS);
            int y   = rem / PADS;
            int xp  = rem % PADS;
            float val = 0.f;
            if (y >= 1 && y <= H && xp >= 1 && xp <= W)
                val = inb[(cc + c) * HW + (y - 1) * W + (xp - 1)];
            s_in[i] = val;
        }
        // stage weights (already laid out [cin][k][co16], contiguous slice)
        for (int i = tid; i < CCH * 144; i += NTHREADS)
            s_w[i] = wtb[cc * 144 + i];
        __syncthreads();

        if (active) {
#pragma unroll 1
            for (int c = 0; c < CCH; c++) {
                float wv[9];
#pragma unroll
                for (int k = 0; k < 9; k++) wv[k] = s_w[c * 144 + k * 16 + co];
                const float* base = &s_in[c * 21 * PADS];
#pragma unroll
                for (int ky = 0; ky < 3; ky++) {
                    const float4* rp =
                        reinterpret_cast<const float4*>(base + (row + ky) * PADS);
                    float rr[24];
#pragma unroll
                    for (int j = 0; j < 6; j++) {
                        float4 q = rp[j];
                        rr[4 * j + 0] = q.x; rr[4 * j + 1] = q.y;
                        rr[4 * j + 2] = q.z; rr[4 * j + 3] = q.w;
                    }
#pragma unroll
                    for (int kx = 0; kx < 3; kx++) {
                        float wgt = wv[ky * 3 + kx];
#pragma unroll
                        for (int x = 0; x < W; x++)
                            acc[x] = fmaf(wgt, rr[x + kx], acc[x]);
                    }
                }
            }
        }
        __syncthreads();
    }

    if (!active) return;
    int coutg = chunk * COUT_T + co;
    if (MODE == 0) {
        if (coutg < CR) {
            float* p = g_reg + ((size_t)img * CR + coutg) * HW + row * W;
#pragma unroll
            for (int x = 0; x < W; x++) p[x] = acc[x];
        } else {
            int c2 = coutg - CR;
            float sc = bg[c2] * rsqrtf(bv[c2] + EPS);
            float bs = fmaf(-bm[c2], sc, bb[c2]);
            float* p = g_gp + ((size_t)img * CG + c2) * HW + row * W;
#pragma unroll
            for (int x = 0; x < W; x++) p[x] = mishf(fmaf(acc[x], sc, bs));
        }
    } else {
        size_t off = ((size_t)img * CT + coutg) * HW + (size_t)row * W;
        const float* rx = resid + off;
        float* p = outp + off;
#pragma unroll
        for (int x = 0; x < W; x++) p[x] = acc[x] + rx[x];
    }
}

// ---- gpool (mean, 0.5*mean, max over 19x19) + linear [192x192] ----
__global__ void k_gpool(const float* __restrict__ wlin) {
    int img  = blockIdx.x;
    int tid  = threadIdx.x;           // 256 threads
    int warp = tid / 32, lane = tid % 32;
    __shared__ float pooled[3 * CG];  // [mean | 0.5*mean | max]

    for (int c = warp; c < CG; c += 8) {
        const float* p = g_gp + ((size_t)img * CG + c) * HW;
        float s = 0.f, mx = -INFINITY;
        for (int i = lane; i < HW; i += 32) {
            float v = p[i];
            s += v;
            mx = fmaxf(mx, v);
        }
#pragma unroll
        for (int off = 16; off; off >>= 1) {
            s  += __shfl_down_sync(0xFFFFFFFFu, s, off);
            mx = fmaxf(mx, __shfl_down_sync(0xFFFFFFFFu, mx, off));
        }
        if (lane == 0) {
            float mean = s * (1.f / 361.f);
            pooled[c]          = mean;
            pooled[CG + c]     = mean * 0.5f;   // (sqrt(361)-14)/10
            pooled[2 * CG + c] = mx;
        }
    }
    __syncthreads();
    if (tid < CR) {
        float s = 0.f;
        const float* wr = wlin + tid * (3 * CG);
#pragma unroll 4
        for (int k = 0; k < 3 * CG; k++) s = fmaf(pooled[k], wr[k], s);
        g_gpo[img * CR + tid] = s;
    }
}

// ---- stage 4: act2 = mish(bn2(reg + gpo)) ----
__global__ void k_mid(const float* __restrict__ g, const float* __restrict__ b,
                      const float* __restrict__ m, const float* __restrict__ v) {
    int i = blockIdx.x * blockDim.x + threadIdx.x;
    if (i >= Bn * CR * HW) return;
    int c  = (i / HW) % CR;
    int bi = i / (CR * HW);
    float val = g_reg[i] + g_gpo[bi * CR + c];
    float sc = g[c] * rsqrtf(v[c] + EPS);
    float bs = fmaf(-m[c], sc, b[c]);
    g_act2[i] = mishf(fmaf(val, sc, bs));
}

extern "C" void kernel_launch(void* const* d_in, const int* in_sizes, int n_in,
                              void* d_out, int out_size) {
    const float* x    = (const float*)d_in[0];
    const float* b1g  = (const float*)d_in[1];
    const float* b1b  = (const float*)d_in[2];
    const float* b1m  = (const float*)d_in[3];
    const float* b1v  = (const float*)d_in[4];
    const float* w1a  = (const float*)d_in[5];
    const float* w1b  = (const float*)d_in[6];
    const float* bgg  = (const float*)d_in[7];
    const float* bgb  = (const float*)d_in[8];
    const float* bgm  = (const float*)d_in[9];
    const float* bgv  = (const float*)d_in[10];
    const float* wlin = (const float*)d_in[11];
    const float* b2g  = (const float*)d_in[12];
    const float* b2b  = (const float*)d_in[13];
    const float* b2m  = (const float*)d_in[14];
    const float* b2v  = (const float*)d_in[15];
    const float* w2   = (const float*)d_in[16];
    float* out = (float*)d_out;

    k_wt1<<<(16 * CT * 144 + 255) / 256, 256>>>(w1a, w1b);
    k_wt2<<<(16 * CR * 144 + 255) / 256, 256>>>(w2);
    k_pre<<<(Bn * CT * HW + 255) / 256, 256>>>(x, b1g, b1b, b1m, b1v);

    dim3 gconv(16, Bn);
    k_conv<CT, 0><<<gconv, NTHREADS>>>(bgg, bgb, bgm, bgv, nullptr, nullptr);
    k_gpool<<<Bn, 256>>>(wlin);
    k_mid<<<(Bn * CR * HW + 255) / 256, 256>>>(b2g, b2b, b2m, b2v);
    k_conv<CR, 1><<<gconv, NTHREADS>>>(nullptr, nullptr, nullptr, nullptr, x, out);
}

// round 2
// speedup vs baseline: 1.4713x; 1.4713x over previous
#include <cuda_runtime.h>
#include <math.h>

#define EPS 1e-5f

constexpr int Bn = 256;   // batch
constexpr int CT = 256;   // trunk channels
constexpr int CR = 192;   // reg channels
constexpr int CG = 64;    // gpool channels
constexpr int H = 19, W = 19, HW = 361;
constexpr int PY = 21, PX = 24;      // padded plane 21 x 24 (zero border, 16B-aligned rows)
constexpr int PP = PY * PX;          // 504 floats per padded channel plane
constexpr int CCH = 8;               // cin per smem stage
constexpr int NTHREADS = 320;        // 20 rows * 16 couts

// ---- scratch (device globals; no allocation allowed) ----
__device__ float g_act1p[Bn * CT * PP];        // mish(bn1(x)), zero-padded planes
__device__ float g_act2p[Bn * CR * PP];        // mish(bn2(reg+gpo)), zero-padded planes
__device__ float g_reg [Bn * CR * HW];         // conv1a raw output
__device__ float g_gp  [Bn * CG * HW];         // mish(bn1b(conv1b))
__device__ float g_gpo [Bn * CR];              // gpool @ w_lin.T
__device__ float g_w1t [8 * CT * 288];         // [chunk32][cin][k9][co16][pair2]
__device__ float g_w2t [8 * CR * 288];

__device__ __forceinline__ float mishf(float x) {
    // x * tanh(softplus(x)) == x * (t^2 + 2t) / (t^2 + 2t + 2), t = e^x
    if (x > 20.f) return x;
    float t = __expf(x);
    float u = fmaf(t, t, 2.f * t);
    return x * __fdividef(u, u + 2.f);
}

// ---- weight transforms: OIHW -> [chunk][cin][k][co*2+h], cout = chunk*32 + co + 16h ----
__global__ void k_wt1(const float* __restrict__ w1a, const float* __restrict__ w1b) {
    int i = blockIdx.x * blockDim.x + threadIdx.x;
    if (i >= 8 * CT * 288) return;
    int chunk = i / (CT * 288);
    int rem   = i % (CT * 288);
    int cin   = rem / 288;
    int r2    = rem % 288;
    int k     = r2 / 32;
    int j     = r2 % 32;
    int cout  = chunk * 32 + (j >> 1) + 16 * (j & 1);
    g_w1t[i] = (cout < CR) ? w1a[(cout * CT + cin) * 9 + k]
                           : w1b[((cout - CR) * CT + cin) * 9 + k];
}

__global__ void k_wt2(const float* __restrict__ w2) {
    int i = blockIdx.x * blockDim.x + threadIdx.x;
    if (i >= 8 * CR * 288) return;
    int chunk = i / (CR * 288);
    int rem   = i % (CR * 288);
    int cin   = rem / 288;
    int r2    = rem % 288;
    int k     = r2 / 32;
    int j     = r2 % 32;
    int cout  = chunk * 32 + (j >> 1) + 16 * (j & 1);
    g_w2t[i] = w2[(cout * CR + cin) * 9 + k];
}

// ---- stage 1: act1p = pad(mish(bn1(x))), one block per (img, c) plane ----
__global__ void k_pre(const float* __restrict__ x,
                      const float* __restrict__ g, const float* __restrict__ b,
                      const float* __restrict__ m, const float* __restrict__ v) {
    int bx  = blockIdx.x;
    int img = bx / CT, c = bx % CT;
    float sc = g[c] * rsqrtf(v[c] + EPS);
    float bs = fmaf(-m[c], sc, b[c]);
    const float* xp = x + (size_t)bx * HW;
    float* op = g_act1p + (size_t)bx * PP;
    for (int i = threadIdx.x; i < PP; i += blockDim.x) {
        int y = i / PX, xc = i % PX;
        float val = 0.f;
        if (y >= 1 && y <= H && xc >= 1 && xc <= W)
            val = mishf(fmaf(xp[(y - 1) * W + (xc - 1)], sc, bs));
        op[i] = val;
    }
}

// ---- stage 4: act2p = pad(mish(bn2(reg + gpo))) ----
__global__ void k_mid(const float* __restrict__ g, const float* __restrict__ b,
                      const float* __restrict__ m, const float* __restrict__ v) {
    int bx  = blockIdx.x;
    int img = bx / CR, c = bx % CR;
    float sc = g[c] * rsqrtf(v[c] + EPS);
    float bs = fmaf(-m[c], sc, b[c]);
    float gv = g_gpo[img * CR + c];
    const float* rp = g_reg + (size_t)bx * HW;
    float* op = g_act2p + (size_t)bx * PP;
    for (int i = threadIdx.x; i < PP; i += blockDim.x) {
        int y = i / PX, xc = i % PX;
        float val = 0.f;
        if (y >= 1 && y <= H && xc >= 1 && xc <= W)
            val = mishf(fmaf(rp[(y - 1) * W + (xc - 1)] + gv, sc, bs));
        op[i] = val;
    }
}

// ---- 3x3 SAME conv, direct fp32, 32 couts/block (2 per thread) ----
// MODE 0: in=act1p (CIN=256); cout<192 -> g_reg; cout>=192 -> mish(bn1b) -> g_gp
// MODE 1: in=act2p (CIN=192); out = conv + resid(x)
template <int CIN, int MODE>
__global__ __launch_bounds__(NTHREADS, 2)
void k_conv(const float* __restrict__ bg, const float* __restrict__ bb,
            const float* __restrict__ bm, const float* __restrict__ bv,
            const float* __restrict__ resid, float* __restrict__ outp) {
    __shared__ __align__(16) float s_in[CCH * PP];    // 8*504*4 = 16128 B
    __shared__ __align__(16) float s_w[CCH * 288];    //  8*288*4 =  9216 B

    const float* in = (MODE == 0) ? g_act1p : g_act2p;
    const float* wt = (MODE == 0) ? g_w1t : g_w2t;

    const int chunk = blockIdx.x;
    const int img   = blockIdx.y;
    const int tid   = threadIdx.x;
    const int row   = tid >> 4;
    const int co    = tid & 15;
    const bool active = (row < H);

    float acc[2][W];
#pragma unroll
    for (int x = 0; x < W; x++) { acc[0][x] = 0.f; acc[1][x] = 0.f; }

    const float4* src  = reinterpret_cast<const float4*>(in + (size_t)img * CIN * PP);
    const float4* wsrc = reinterpret_cast<const float4*>(wt + (size_t)chunk * CIN * 288);

    for (int cc = 0; cc < CIN; cc += CCH) {
        // straight float4 copies; borders were pre-zeroed in gmem
        const float4* s4 = src + cc * (PP / 4);
#pragma unroll 1
        for (int i = tid; i < CCH * PP / 4; i += NTHREADS)
            reinterpret_cast<float4*>(s_in)[i] = s4[i];
        const float4* w4 = wsrc + cc * 72;
#pragma unroll 1
        for (int i = tid; i < CCH * 72; i += NTHREADS)
            reinterpret_cast<float4*>(s_w)[i] = w4[i];
        __syncthreads();

        if (active) {
#pragma unroll 2
            for (int c = 0; c < CCH; c++) {
                const float* base = s_in + c * PP + row * PX;
                const float* wb   = s_w + c * 288 + co * 2;
#pragma unroll
                for (int ky = 0; ky < 3; ky++) {
                    float rr[24];
                    const float4* rp = reinterpret_cast<const float4*>(base + ky * PX);
#pragma unroll
                    for (int j = 0; j < 6; j++)
                        *reinterpret_cast<float4*>(&rr[4 * j]) = rp[j];
#pragma unroll
                    for (int kx = 0; kx < 3; kx++) {
                        float2 w = *reinterpret_cast<const float2*>(&wb[(ky * 3 + kx) * 32]);
#pragma unroll
                        for (int x = 0; x < W; x++) {
                            acc[0][x] = fmaf(w.x, rr[x + kx], acc[0][x]);
                            acc[1][x] = fmaf(w.y, rr[x + kx], acc[1][x]);
                        }
                    }
                }
            }
        }
        __syncthreads();
    }

    if (!active) return;
#pragma unroll
    for (int h = 0; h < 2; h++) {
        int cg = chunk * 32 + co + 16 * h;
        if (MODE == 0) {
            if (cg < CR) {
                float* p = g_reg + ((size_t)img * CR + cg) * HW + row * W;
#pragma unroll
                for (int x = 0; x < W; x++) p[x] = acc[h][x];
            } else {
                int c2 = cg - CR;
                float sc = bg[c2] * rsqrtf(bv[c2] + EPS);
                float bs = fmaf(-bm[c2], sc, bb[c2]);
                float* p = g_gp + ((size_t)img * CG + c2) * HW + row * W;
#pragma unroll
                for (int x = 0; x < W; x++) p[x] = mishf(fmaf(acc[h][x], sc, bs));
            }
        } else {
            size_t off = ((size_t)img * CT + cg) * HW + (size_t)row * W;
            const float* rx = resid + off;
            float* p = outp + off;
#pragma unroll
            for (int x = 0; x < W; x++) p[x] = acc[h][x] + rx[x];
        }
    }
}

// ---- gpool (mean, 0.5*mean, max over 19x19) + linear [192 x 192] ----
__global__ void k_gpool(const float* __restrict__ wlin) {
    int img  = blockIdx.x;
    int tid  = threadIdx.x;           // 256 threads
    int warp = tid / 32, lane = tid % 32;
    __shared__ float pooled[3 * CG];

    for (int c = warp; c < CG; c += 8) {
        const float* p = g_gp + ((size_t)img * CG + c) * HW;
        float s = 0.f, mx = -INFINITY;
        for (int i = lane; i < HW; i += 32) {
            float v = p[i];
            s += v;
            mx = fmaxf(mx, v);
        }
#pragma unroll
        for (int off = 16; off; off >>= 1) {
            s  += __shfl_down_sync(0xFFFFFFFFu, s, off);
            mx = fmaxf(mx, __shfl_down_sync(0xFFFFFFFFu, mx, off));
        }
        if (lane == 0) {
            float mean = s * (1.f / 361.f);
            pooled[c]          = mean;
            pooled[CG + c]     = mean * 0.5f;   // (sqrt(361)-14)/10
            pooled[2 * CG + c] = mx;
        }
    }
    __syncthreads();
    if (tid < CR) {
        float s = 0.f;
        const float* wr = wlin + tid * (3 * CG);
#pragma unroll 4
        for (int k = 0; k < 3 * CG; k++) s = fmaf(pooled[k], wr[k], s);
        g_gpo[img * CR + tid] = s;
    }
}

extern "C" void kernel_launch(void* const* d_in, const int* in_sizes, int n_in,
                              void* d_out, int out_size) {
    const float* x    = (const float*)d_in[0];
    const float* b1g  = (const float*)d_in[1];
    const float* b1b  = (const float*)d_in[2];
    const float* b1m  = (const float*)d_in[3];
    const float* b1v  = (const float*)d_in[4];
    const float* w1a  = (const float*)d_in[5];
    const float* w1b  = (const float*)d_in[6];
    const float* bgg  = (const float*)d_in[7];
    const float* bgb  = (const float*)d_in[8];
    const float* bgm  = (const float*)d_in[9];
    const float* bgv  = (const float*)d_in[10];
    const float* wlin = (const float*)d_in[11];
    const float* b2g  = (const float*)d_in[12];
    const float* b2b  = (const float*)d_in[13];
    const float* b2m  = (const float*)d_in[14];
    const float* b2v  = (const float*)d_in[15];
    const float* w2   = (const float*)d_in[16];
    float* out = (float*)d_out;

    k_wt1<<<(8 * CT * 288 + 255) / 256, 256>>>(w1a, w1b);
    k_wt2<<<(8 * CR * 288 + 255) / 256, 256>>>(w2);
    k_pre<<<Bn * CT, 128>>>(x, b1g, b1b, b1m, b1v);

    dim3 gconv(8, Bn);
    k_conv<CT, 0><<<gconv, NTHREADS>>>(bgg, bgb, bgm, bgv, nullptr, nullptr);
    k_gpool<<<Bn, 256>>>(wlin);
    k_mid<<<Bn * CR, 128>>>(b2g, b2b, b2m, b2v);
    k_conv<CR, 1><<<gconv, NTHREADS>>>(nullptr, nullptr, nullptr, nullptr, x, out);
}